// round 16
// baseline (speedup 1.0000x reference)
#include <cuda_runtime.h>
#include <cuda_bf16.h>
#include <cstdint>

// Sparsemax along last dim (n = 512) of a (64, 1024, 512) fp32 tensor.
// One warp per row, 16 elements/lane.
//
// tau* >= max(z)-1, so the support is a subset of C = {z > max-1} (~7 elems
// for N(0,1) rows). Candidates are compacted (<=2 regs/lane), gathered into
// a 16-slot smem array, and tau* is computed in CLOSED FORM:
//     tau* = max_j (sum_{c_i >= c_j} c_i - 1) / #{c_i >= c_j}
// (t(k) is unimodal in k, so the max over pivot hypotheses equals the
// sort-based threshold; ties are handled block-complete). This replaces the
// data-dependent Michelot iteration (~4 serial SHFL ladders) with one
// gather + local scan + a single 4-step fmax ladder.
//
// Non-candidates output exactly 0 (z <= max-1 <= tau*), so the epilogue is
// zero-stores plus <=2 scattered candidate stores — z dies after compaction,
// keeping register count at the full-occupancy point.

#define ROW_N   512
#define ELEMS   16
#define WARPS_PER_BLOCK 8
#define THREADS (WARPS_PER_BLOCK * 32)
#define FULLM   0xFFFFFFFFu
#define MAXC    16

__device__ __forceinline__ float warp_sum(float v) {
    #pragma unroll
    for (int m = 16; m > 0; m >>= 1)
        v += __shfl_xor_sync(FULLM, v, m);
    return v;
}

__device__ __forceinline__ float warp_max(float v) {
    #pragma unroll
    for (int m = 16; m > 0; m >>= 1)
        v = fmaxf(v, __shfl_xor_sync(FULLM, v, m));
    return v;
}

__global__ __launch_bounds__(THREADS)
void sparsemax_kernel(const float* __restrict__ x,
                      float* __restrict__ out,
                      int rows) {
    __shared__ __align__(16) float cand[WARPS_PER_BLOCK][MAXC];

    const int wwarp   = threadIdx.x >> 5;
    const int warp_id = blockIdx.x * WARPS_PER_BLOCK + wwarp;
    if (warp_id >= rows) return;
    const int lane = threadIdx.x & 31;

    const float4* __restrict__ xin =
        reinterpret_cast<const float4*>(x + (size_t)warp_id * ROW_N);

    // Coalesced load: lane l reads float4s l, l+32, l+64, l+96.
    float z[ELEMS];
    #pragma unroll
    for (int j = 0; j < 4; j++) {
        float4 v = xin[lane + 32 * j];
        z[4 * j + 0] = v.x;
        z[4 * j + 1] = v.y;
        z[4 * j + 2] = v.z;
        z[4 * j + 3] = v.w;
    }

    // Row max -> candidate threshold thr = m - 1 (tau* >= thr).
    float m = z[0];
    #pragma unroll
    for (int i = 1; i < ELEMS; i++) m = fmaxf(m, z[i]);
    m = warp_max(m);
    const float thr = m - 1.0f;

    // Compact candidates {z > thr} into (v0,i0),(v1,i1).
    // Element j of this lane sits at column 4*lane + off_j, off_j = 128*(j/4)+(j%4).
    const float NEG_INF = __int_as_float(0xff800000);
    float v0 = NEG_INF, v1 = NEG_INF;
    int   i0 = 0,       i1 = 0;
    int   nc = 0;
    #pragma unroll
    for (int j = 0; j < ELEMS; j++) {
        const int off = 128 * (j >> 2) + (j & 3);
        bool g = z[j] > thr;
        v1 = g ? v0 : v1;
        i1 = g ? i0 : i1;
        v0 = g ? z[j] : v0;
        i0 = g ? off  : i0;
        nc += g ? 1 : 0;
    }

    const unsigned b0 = __ballot_sync(FULLM, nc >= 1);
    const unsigned b1 = __ballot_sync(FULLM, nc >= 2);
    const unsigned bo = __ballot_sync(FULLM, nc > 2);
    const int k = __popc(b0) + __popc(b1);

    float tau;
    if (bo == 0u && k <= MAXC) {
        // ---- fast path: gather candidates, closed-form tau ----
        const unsigned lt = (1u << lane) - 1u;
        if (lane < MAXC && lane >= k) cand[wwarp][lane] = NEG_INF;
        if (nc >= 1) cand[wwarp][__popc(b0 & lt)] = v0;
        if (nc >= 2) cand[wwarp][__popc(b0) + __popc(b1 & lt)] = v1;
        __syncwarp(FULLM);

        const float piv = cand[wwarp][lane & 15];
        const float4 c0 = *reinterpret_cast<const float4*>(&cand[wwarp][0]);
        const float4 c1 = *reinterpret_cast<const float4*>(&cand[wwarp][4]);
        const float4 c2 = *reinterpret_cast<const float4*>(&cand[wwarp][8]);
        const float4 c3 = *reinterpret_cast<const float4*>(&cand[wwarp][12]);

        float s = 0.0f;
        int   c = 0;
        #define ACC(cc) do { if ((cc) >= piv) { s += (cc); c++; } } while (0)
        ACC(c0.x); ACC(c0.y); ACC(c0.z); ACC(c0.w);
        ACC(c1.x); ACC(c1.y); ACC(c1.z); ACC(c1.w);
        ACC(c2.x); ACC(c2.y); ACC(c2.z); ACC(c2.w);
        ACC(c3.x); ACC(c3.y); ACC(c3.z); ACC(c3.w);
        #undef ACC

        float t = __fdividef(s - 1.0f, (float)c);
        // Lanes 16-31 mirror lanes 0-15 (same pivot slots), so a 4-step
        // ladder over each 16-lane half yields the global max in all lanes.
        #pragma unroll
        for (int off = 8; off > 0; off >>= 1)
            t = fmaxf(t, __shfl_xor_sync(FULLM, t, off));
        tau = t;

        // Epilogue: zeros everywhere, then scatter the <=2 candidate outputs.
        float4* __restrict__ o =
            reinterpret_cast<float4*>(out + (size_t)warp_id * ROW_N);
        const float4 zero4 = make_float4(0.0f, 0.0f, 0.0f, 0.0f);
        #pragma unroll
        for (int j = 0; j < 4; j++) o[lane + 32 * j] = zero4;
        float* __restrict__ os = out + (size_t)warp_id * ROW_N + 4 * lane;
        if (nc >= 1) os[i0] = fmaxf(v0 - tau, 0.0f);
        if (nc >= 2) os[i1] = fmaxf(v1 - tau, 0.0f);
    } else {
        // ---- fallback (rare, warp-uniform): full Michelot on z ----
        float ps = 0.0f;
        int   pc = 0;
        #pragma unroll
        for (int i = 0; i < ELEMS; i++) {
            bool g = z[i] > thr;
            ps += g ? z[i] : 0.0f;
            pc += g ? 1 : 0;
        }
        ps = warp_sum(ps);
        pc = __reduce_add_sync(FULLM, pc);
        tau = __fdividef(ps - 1.0f, (float)pc);
        int cnt = pc;

        #pragma unroll 1
        for (int it = 0; it < 48; it++) {
            float s = 0.0f;
            int   c = 0;
            #pragma unroll
            for (int i = 0; i < ELEMS; i++) {
                bool g = z[i] > tau;
                s += g ? z[i] : 0.0f;
                c += g ? 1 : 0;
            }
            s = warp_sum(s);
            c = __reduce_add_sync(FULLM, c);
            if (c == cnt) break;
            cnt = c;
            tau = __fdividef(s - 1.0f, (float)c);
        }

        float4* __restrict__ o =
            reinterpret_cast<float4*>(out + (size_t)warp_id * ROW_N);
        #pragma unroll
        for (int j = 0; j < 4; j++) {
            float4 v;
            v.x = fmaxf(z[4 * j + 0] - tau, 0.0f);
            v.y = fmaxf(z[4 * j + 1] - tau, 0.0f);
            v.z = fmaxf(z[4 * j + 2] - tau, 0.0f);
            v.w = fmaxf(z[4 * j + 3] - tau, 0.0f);
            o[lane + 32 * j] = v;
        }
    }
}

extern "C" void kernel_launch(void* const* d_in, const int* in_sizes, int n_in,
                              void* d_out, int out_size) {
    const float* x = (const float*)d_in[0];
    float* out = (float*)d_out;
    const int rows = in_sizes[0] / ROW_N;   // 65536
    const int blocks = (rows + WARPS_PER_BLOCK - 1) / WARPS_PER_BLOCK;
    sparsemax_kernel<<<blocks, THREADS>>>(x, out, rows);
}